// round 12
// baseline (speedup 1.0000x reference)
#include <cuda_runtime.h>
#include <cuda_bf16.h>
#include <cstdint>

// ---------------------------------------------------------------------------
// Problem constants
// ---------------------------------------------------------------------------
#define MDIM 4096
#define NDIM 4096
#define KDIM 4096
#define BLK  128

#define BM 128
#define BN 128
#define BK 32                      // K per pipeline stage (2 x k16 steps)
#define NSTAGE 4
#define NKITER (KDIM / BK)         // 128

// Fragment-native tiled layouts (mma.m16n8k16.bf16):
//   A tile = 16(m) x 16(k) bf16 = 512B, per-lane 8 halves at lane*16
//   B tile =  8(n) x 16(k) bf16 = 256B, per-lane 4 halves at lane*8
// Stage SMEM: A = [plane(2)][mt(8)][kt(2)][512B] = 16 KB
//             B = [plane(2)][nt(16)][kt(2)][256B] = 16 KB
#define A_STAGE_BYTES 16384
#define B_STAGE_BYTES 16384
#define STAGE_BYTES   (A_STAGE_BYTES + B_STAGE_BYTES)      // 32 KB
#define SMEM_BYTES    (NSTAGE * STAGE_BYTES)               // 128 KB

// ---------------------------------------------------------------------------
// Scratch: hi/lo bf16 planes (scale-folded), fragment-ordered. 32 MB each.
// ---------------------------------------------------------------------------
__device__ __nv_bfloat16 g_xh[(size_t)MDIM * KDIM];
__device__ __nv_bfloat16 g_xl[(size_t)MDIM * KDIM];
__device__ __nv_bfloat16 g_wh[(size_t)NDIM * KDIM];
__device__ __nv_bfloat16 g_wl[(size_t)NDIM * KDIM];

// ---------------------------------------------------------------------------
// Helpers
// ---------------------------------------------------------------------------
__device__ __forceinline__ uint32_t smem_u32(const void* p) {
    uint32_t a;
    asm("{ .reg .u64 t; cvta.to.shared.u64 t, %1; cvt.u32.u64 %0, t; }"
        : "=r"(a) : "l"(p));
    return a;
}

__device__ __forceinline__ void cp_async16(uint32_t dst, const void* src) {
    asm volatile("cp.async.cg.shared.global [%0], [%1], 16;" :: "r"(dst), "l"(src));
}
#define CP_COMMIT()  asm volatile("cp.async.commit_group;" ::: "memory")
#define CP_WAIT(n)   asm volatile("cp.async.wait_group %0;" :: "n"(n) : "memory")

__device__ __forceinline__ void mma_bf16(float* c, const uint4& a, const uint2& b) {
    asm volatile(
        "mma.sync.aligned.m16n8k16.row.col.f32.bf16.bf16.f32 "
        "{%0,%1,%2,%3}, {%4,%5,%6,%7}, {%8,%9}, {%0,%1,%2,%3};"
        : "+f"(c[0]), "+f"(c[1]), "+f"(c[2]), "+f"(c[3])
        : "r"(a.x), "r"(a.y), "r"(a.z), "r"(a.w), "r"(b.x), "r"(b.y));
}

// Split a float2 into packed-bf16 hi and lo words (low half = .x).
__device__ __forceinline__ void split2(float2 v, uint32_t& h, uint32_t& l) {
    __nv_bfloat16 hx = __float2bfloat16(v.x);
    __nv_bfloat16 hy = __float2bfloat16(v.y);
    __nv_bfloat16 lx = __float2bfloat16(v.x - __bfloat162float(hx));
    __nv_bfloat16 ly = __float2bfloat16(v.y - __bfloat162float(hy));
    h = (uint32_t)__bfloat16_as_ushort(hx) | ((uint32_t)__bfloat16_as_ushort(hy) << 16);
    l = (uint32_t)__bfloat16_as_ushort(lx) | ((uint32_t)__bfloat16_as_ushort(ly) << 16);
}

// bf16-quantize a value but keep fp32 storage (reference casts to bf16; the
// harness output buffer is fp32).
__device__ __forceinline__ float bf16r(float v) {
    return __bfloat162float(__float2bfloat16(v));
}

// ---------------------------------------------------------------------------
// Dequant + split + fragment re-layout. Block = 32 rows x 128 k.
// SMEM staged with 33-float4 row stride (132 floats).
// ---------------------------------------------------------------------------
__global__ __launch_bounds__(256) void dequant_x_kernel(
    const float* __restrict__ x, const float* __restrict__ xs) {
    __shared__ float4 sm4[32 * 33];
    const int tid = threadIdx.x;
    const int kb  = blockIdx.x;            // 128-wide k block, 0..31
    const int m0  = blockIdx.y * 32;

#pragma unroll
    for (int j = 0; j < 4; ++j) {
        int i   = tid + 256 * j;
        int row = i >> 5;
        int c4  = i & 31;
        float s  = xs[(size_t)(m0 + row) * (KDIM / BLK) + kb];
        float4 v = *(const float4*)(x + (size_t)(m0 + row) * KDIM + kb * BLK + c4 * 4);
        v.x *= s; v.y *= s; v.z *= s; v.w *= s;
        sm4[row * 33 + c4] = v;
    }
    __syncthreads();

    const float* smf = (const float*)sm4;  // row stride 132 floats
    const int w = tid >> 5, lane = tid & 31;
    const int g = lane >> 2, t = lane & 3;
    // A tiles in block: 2 MT x 8 KT = 16 ; warp handles 2.
#pragma unroll
    for (int jj = 0; jj < 2; ++jj) {
        int T  = w * 2 + jj;
        int mt = T >> 3;
        int kt = T & 7;
        const float* base = smf + (mt * 16 + g) * 132 + kt * 16 + 2 * t;
        float2 e00 = *(const float2*)(base);             // row g,   k 2t,2t+1
        float2 e10 = *(const float2*)(base + 8 * 132);   // row g+8, k 2t,2t+1
        float2 e01 = *(const float2*)(base + 8);         // row g,   k 2t+8,+9
        float2 e11 = *(const float2*)(base + 8 * 132 + 8);
        uint4 H, L;
        split2(e00, H.x, L.x);   // a0
        split2(e10, H.y, L.y);   // a1
        split2(e01, H.z, L.z);   // a2
        split2(e11, H.w, L.w);   // a3
        size_t MT = (size_t)(m0 >> 4) + mt;
        size_t KT = (size_t)kb * 8 + kt;
        size_t tb = (MT * 256 + KT) * 256;     // bf16 elems
        reinterpret_cast<uint4*>(g_xh + tb)[lane] = H;
        reinterpret_cast<uint4*>(g_xl + tb)[lane] = L;
    }
}

__global__ __launch_bounds__(256) void dequant_w_kernel(
    const float* __restrict__ wgt, const float* __restrict__ ws) {
    __shared__ float4 sm4[32 * 33];
    const int tid = threadIdx.x;
    const int kb  = blockIdx.x;
    const int n0  = blockIdx.y * 32;
    const float s = ws[(size_t)(n0 >> 7) * (KDIM / BLK) + kb];

#pragma unroll
    for (int j = 0; j < 4; ++j) {
        int i   = tid + 256 * j;
        int row = i >> 5;
        int c4  = i & 31;
        float4 v = *(const float4*)(wgt + (size_t)(n0 + row) * KDIM + kb * BLK + c4 * 4);
        v.x *= s; v.y *= s; v.z *= s; v.w *= s;
        sm4[row * 33 + c4] = v;
    }
    __syncthreads();

    const float* smf = (const float*)sm4;
    const int w = tid >> 5, lane = tid & 31;
    const int g = lane >> 2, t = lane & 3;
    // B tiles in block: 4 NT x 8 KT = 32 ; warp handles 4.
#pragma unroll
    for (int jj = 0; jj < 4; ++jj) {
        int T  = w * 4 + jj;
        int nt = T >> 3;
        int kt = T & 7;
        const float* base = smf + (nt * 8 + g) * 132 + kt * 16 + 2 * t;
        float2 e0 = *(const float2*)(base);      // k 2t, 2t+1
        float2 e1 = *(const float2*)(base + 8);  // k 2t+8, 2t+9
        uint2 H, L;
        split2(e0, H.x, L.x);   // b0
        split2(e1, H.y, L.y);   // b1
        size_t NT = (size_t)(n0 >> 3) + nt;
        size_t KT = (size_t)kb * 8 + kt;
        size_t tb = (NT * 256 + KT) * 128;
        reinterpret_cast<uint2*>(g_wh + tb)[lane] = H;
        reinterpret_cast<uint2*>(g_wl + tb)[lane] = L;
    }
}

// ---------------------------------------------------------------------------
// GEMM: y = xd . wd^T via bf16x3 (hh + hl + lh), fp32 accumulate.
// 256 threads, 8 warps 2(m) x 4(n), warp tile 64x32, mma.m16n8k16.bf16.
// ---------------------------------------------------------------------------
__global__ __launch_bounds__(256, 1)
void gemm_bf16x3_kernel(float* __restrict__ out) {
    extern __shared__ char smem[];
    const uint32_t su = smem_u32(smem);
    const int tid  = threadIdx.x;
    const int wid  = tid >> 5;
    const int lane = tid & 31;
    const int warp_m = wid >> 2;
    const int warp_n = wid & 3;

    const int MT0 = blockIdx.y * 8;     // A tile rows (16m each)
    const int NT0 = blockIdx.x * 16;    // B tile rows (8n each)

    // ---- cp.async mapping: 4 A + 4 B 16B chunks per thread -----------------
    const char* aSrc[4];
    const char* bSrc[4];
    uint32_t aDst[4], bDst[4];
#pragma unroll
    for (int j = 0; j < 4; ++j) {
        int c = tid + 256 * j;                         // 0..1023
        {   // A: [plane(2)][mt(8)][64 chunks]
            int plane = c >> 9;
            int mt    = (c >> 6) & 7;
            int off   = (c & 63) * 16;
            const __nv_bfloat16* pl = plane ? g_xl : g_xh;
            // MT row stride = 256 KT * 512B = 131072B ; stage adds kt*1024B
            aSrc[j] = (const char*)pl + (size_t)(MT0 + mt) * 131072 + off;
            aDst[j] = (uint32_t)(plane * 8192 + mt * 1024 + off);
        }
        {   // B: [plane(2)][nt(16)][32 chunks]
            int plane = c >> 9;
            int nt    = (c >> 5) & 15;
            int off   = (c & 31) * 16;
            const __nv_bfloat16* pl = plane ? g_wl : g_wh;
            // NT row stride = 256 KT * 256B = 65536B ; stage adds kt*512B
            bSrc[j] = (const char*)pl + (size_t)(NT0 + nt) * 65536 + off;
            bDst[j] = (uint32_t)(A_STAGE_BYTES + plane * 8192 + nt * 512 + off);
        }
    }

    // ---- fragment LDS offsets ---------------------------------------------
    uint32_t aOff[4], bOff[4];
#pragma unroll
    for (int mi = 0; mi < 4; ++mi)
        aOff[mi] = (uint32_t)((warp_m * 4 + mi) * 1024 + lane * 16);
#pragma unroll
    for (int ni = 0; ni < 4; ++ni)
        bOff[ni] = (uint32_t)(A_STAGE_BYTES + (warp_n * 4 + ni) * 512 + lane * 8);

    float acc[4][4][4];
#pragma unroll
    for (int mi = 0; mi < 4; ++mi)
#pragma unroll
        for (int ni = 0; ni < 4; ++ni)
#pragma unroll
            for (int i = 0; i < 4; ++i) acc[mi][ni][i] = 0.0f;

    // ---- prologue ----------------------------------------------------------
#pragma unroll
    for (int p = 0; p < NSTAGE - 1; ++p) {
        const uint32_t sb = su + p * STAGE_BYTES;
#pragma unroll
        for (int j = 0; j < 4; ++j) cp_async16(sb + aDst[j], aSrc[j] + (size_t)p * 1024);
#pragma unroll
        for (int j = 0; j < 4; ++j) cp_async16(sb + bDst[j], bSrc[j] + (size_t)p * 512);
        CP_COMMIT();
    }

    // ---- mainloop ----------------------------------------------------------
    for (int kt = 0; kt < NKITER; ++kt) {
        CP_WAIT(NSTAGE - 2);
        __syncthreads();

        const int pf = kt + NSTAGE - 1;
        if (pf < NKITER) {
            const uint32_t sb = su + (pf & (NSTAGE - 1)) * STAGE_BYTES;
#pragma unroll
            for (int j = 0; j < 4; ++j) cp_async16(sb + aDst[j], aSrc[j] + (size_t)pf * 1024);
#pragma unroll
            for (int j = 0; j < 4; ++j) cp_async16(sb + bDst[j], bSrc[j] + (size_t)pf * 512);
        }
        CP_COMMIT();

        const char* sb = smem + (kt & (NSTAGE - 1)) * STAGE_BYTES;
#pragma unroll
        for (int ks = 0; ks < 2; ++ks) {          // two k16 steps per stage
            uint4 aH[4], aL[4];
            uint2 bH[4], bL[4];
#pragma unroll
            for (int mi = 0; mi < 4; ++mi) {
                aH[mi] = *reinterpret_cast<const uint4*>(sb + aOff[mi] + ks * 512);
                aL[mi] = *reinterpret_cast<const uint4*>(sb + aOff[mi] + ks * 512 + 8192);
            }
#pragma unroll
            for (int ni = 0; ni < 4; ++ni) {
                bH[ni] = *reinterpret_cast<const uint2*>(sb + bOff[ni] + ks * 256);
                bL[ni] = *reinterpret_cast<const uint2*>(sb + bOff[ni] + ks * 256 + 8192);
            }
#pragma unroll
            for (int mi = 0; mi < 4; ++mi)
#pragma unroll
                for (int ni = 0; ni < 4; ++ni) {
                    mma_bf16(acc[mi][ni], aH[mi], bH[ni]);   // hh
                    mma_bf16(acc[mi][ni], aH[mi], bL[ni]);   // hl
                    mma_bf16(acc[mi][ni], aL[mi], bH[ni]);   // lh
                }
        }
    }

    // ---- epilogue: bf16-quantized values stored as fp32 --------------------
    const int m0 = blockIdx.y * BM;
    const int n0 = blockIdx.x * BN;
    const int mrow = lane >> 2;
    const int ncol = 2 * (lane & 3);
#pragma unroll
    for (int mi = 0; mi < 4; ++mi) {
        const int m = m0 + warp_m * 64 + mi * 16 + mrow;
#pragma unroll
        for (int ni = 0; ni < 4; ++ni) {
            const int n = n0 + warp_n * 32 + ni * 8 + ncol;
            float2 v01 = make_float2(bf16r(acc[mi][ni][0]), bf16r(acc[mi][ni][1]));
            float2 v23 = make_float2(bf16r(acc[mi][ni][2]), bf16r(acc[mi][ni][3]));
            *reinterpret_cast<float2*>(out + (size_t)m * NDIM + n)       = v01;
            *reinterpret_cast<float2*>(out + (size_t)(m + 8) * NDIM + n) = v23;
        }
    }
}

// ---------------------------------------------------------------------------
// Launch — bind inputs by element count (order-independent).
// ---------------------------------------------------------------------------
extern "C" void kernel_launch(void* const* d_in, const int* in_sizes, int n_in,
                              void* d_out, int out_size) {
    int idx_xs = -1, idx_ws = -1, big[2] = {-1, -1};
    int nbig = 0;
    for (int i = 0; i < n_in; ++i) {
        if (in_sizes[i] == MDIM * (KDIM / BLK))              idx_xs = i;  // 131072
        else if (in_sizes[i] == (NDIM / BLK) * (KDIM / BLK)) idx_ws = i;  // 1024
        else if (in_sizes[i] == MDIM * KDIM && nbig < 2)     big[nbig++] = i;
    }
    int idx_x, idx_w;
    if (idx_xs >= 0 && nbig == 2) {
        if      (big[0] == idx_xs - 1) { idx_x = big[0]; idx_w = big[1]; }
        else if (big[1] == idx_xs - 1) { idx_x = big[1]; idx_w = big[0]; }
        else if (big[0] == idx_xs + 1) { idx_x = big[0]; idx_w = big[1]; }
        else if (big[1] == idx_xs + 1) { idx_x = big[1]; idx_w = big[0]; }
        else                           { idx_x = big[0]; idx_w = big[1]; }
    } else { idx_x = 0; idx_xs = 1; idx_w = 2; idx_ws = 3; }

    const float* x  = (const float*)d_in[idx_x];
    const float* xs = (const float*)d_in[idx_xs];
    const float* w  = (const float*)d_in[idx_w];
    const float* ws = (const float*)d_in[idx_ws];
    float* y = (float*)d_out;                  // fp32 output buffer

    cudaFuncSetAttribute(gemm_bf16x3_kernel,
                         cudaFuncAttributeMaxDynamicSharedMemorySize, SMEM_BYTES);

    dim3 dq_grid(KDIM / BLK, MDIM / 32);       // (32, 128)
    dequant_x_kernel<<<dq_grid, 256>>>(x, xs);
    dequant_w_kernel<<<dq_grid, 256>>>(w, ws);

    dim3 grid(NDIM / BN, MDIM / BM);           // (32, 32)
    gemm_bf16x3_kernel<<<grid, 256, SMEM_BYTES>>>(y);
}

// round 13
// speedup vs baseline: 1.6280x; 1.6280x over previous
#include <cuda_runtime.h>
#include <cuda_bf16.h>
#include <cstdint>

// ---------------------------------------------------------------------------
// Problem constants
// ---------------------------------------------------------------------------
#define MDIM 4096
#define NDIM 4096
#define KDIM 4096
#define BLK  128

#define BM 128
#define BN 128
#define BK 32                      // K per pipeline stage (2 x k16 steps)
#define NSTAGE 3
#define NKITER (KDIM / BK)         // 128

// Fragment-native tiled layouts (mma.m16n8k16.bf16):
//   A tile = 16(m) x 16(k) bf16 = 512B, per-lane 8 halves at lane*16
//   B tile =  8(n) x 16(k) bf16 = 256B, per-lane 4 halves at lane*8
// Stage SMEM: A = [plane(2)][mt(8)][kt(2)][512B] = 16 KB
//             B = [plane(2)][nt(16)][kt(2)][256B] = 16 KB
#define A_STAGE_BYTES 16384
#define B_STAGE_BYTES 16384
#define STAGE_BYTES   (A_STAGE_BYTES + B_STAGE_BYTES)      // 32 KB
#define SMEM_BYTES    (NSTAGE * STAGE_BYTES)               // 96 KB -> 2 CTA/SM

// ---------------------------------------------------------------------------
// Scratch: hi/lo bf16 planes (scale-folded), fragment-ordered. 32 MB each.
// ---------------------------------------------------------------------------
__device__ __nv_bfloat16 g_xh[(size_t)MDIM * KDIM];
__device__ __nv_bfloat16 g_xl[(size_t)MDIM * KDIM];
__device__ __nv_bfloat16 g_wh[(size_t)NDIM * KDIM];
__device__ __nv_bfloat16 g_wl[(size_t)NDIM * KDIM];

// ---------------------------------------------------------------------------
// Helpers
// ---------------------------------------------------------------------------
__device__ __forceinline__ uint32_t smem_u32(const void* p) {
    uint32_t a;
    asm("{ .reg .u64 t; cvta.to.shared.u64 t, %1; cvt.u32.u64 %0, t; }"
        : "=r"(a) : "l"(p));
    return a;
}

__device__ __forceinline__ void cp_async16(uint32_t dst, const void* src) {
    asm volatile("cp.async.cg.shared.global [%0], [%1], 16;" :: "r"(dst), "l"(src));
}
#define CP_COMMIT()  asm volatile("cp.async.commit_group;" ::: "memory")
#define CP_WAIT(n)   asm volatile("cp.async.wait_group %0;" :: "n"(n) : "memory")

__device__ __forceinline__ void mma_bf16(float* c, const uint4& a, const uint2& b) {
    asm volatile(
        "mma.sync.aligned.m16n8k16.row.col.f32.bf16.bf16.f32 "
        "{%0,%1,%2,%3}, {%4,%5,%6,%7}, {%8,%9}, {%0,%1,%2,%3};"
        : "+f"(c[0]), "+f"(c[1]), "+f"(c[2]), "+f"(c[3])
        : "r"(a.x), "r"(a.y), "r"(a.z), "r"(a.w), "r"(b.x), "r"(b.y));
}

// Split a float2 into packed-bf16 hi and lo words (low half = .x).
__device__ __forceinline__ void split2(float2 v, uint32_t& h, uint32_t& l) {
    __nv_bfloat16 hx = __float2bfloat16(v.x);
    __nv_bfloat16 hy = __float2bfloat16(v.y);
    __nv_bfloat16 lx = __float2bfloat16(v.x - __bfloat162float(hx));
    __nv_bfloat16 ly = __float2bfloat16(v.y - __bfloat162float(hy));
    h = (uint32_t)__bfloat16_as_ushort(hx) | ((uint32_t)__bfloat16_as_ushort(hy) << 16);
    l = (uint32_t)__bfloat16_as_ushort(lx) | ((uint32_t)__bfloat16_as_ushort(ly) << 16);
}

// bf16-quantize a value but keep fp32 storage (reference casts to bf16; the
// harness output buffer is fp32).
__device__ __forceinline__ float bf16r(float v) {
    return __bfloat162float(__float2bfloat16(v));
}

// ---------------------------------------------------------------------------
// Dequant + split + fragment re-layout. Block = 32 rows x 128 k.
// SMEM staged with 33-float4 row stride (132 floats).
// ---------------------------------------------------------------------------
__global__ __launch_bounds__(256) void dequant_x_kernel(
    const float* __restrict__ x, const float* __restrict__ xs) {
    __shared__ float4 sm4[32 * 33];
    const int tid = threadIdx.x;
    const int kb  = blockIdx.x;            // 128-wide k block, 0..31
    const int m0  = blockIdx.y * 32;

#pragma unroll
    for (int j = 0; j < 4; ++j) {
        int i   = tid + 256 * j;
        int row = i >> 5;
        int c4  = i & 31;
        float s  = xs[(size_t)(m0 + row) * (KDIM / BLK) + kb];
        float4 v = *(const float4*)(x + (size_t)(m0 + row) * KDIM + kb * BLK + c4 * 4);
        v.x *= s; v.y *= s; v.z *= s; v.w *= s;
        sm4[row * 33 + c4] = v;
    }
    __syncthreads();

    const float* smf = (const float*)sm4;  // row stride 132 floats
    const int w = tid >> 5, lane = tid & 31;
    const int g = lane >> 2, t = lane & 3;
    // A tiles in block: 2 MT x 8 KT = 16 ; warp handles 2.
#pragma unroll
    for (int jj = 0; jj < 2; ++jj) {
        int T  = w * 2 + jj;
        int mt = T >> 3;
        int kt = T & 7;
        const float* base = smf + (mt * 16 + g) * 132 + kt * 16 + 2 * t;
        float2 e00 = *(const float2*)(base);             // row g,   k 2t,2t+1
        float2 e10 = *(const float2*)(base + 8 * 132);   // row g+8, k 2t,2t+1
        float2 e01 = *(const float2*)(base + 8);         // row g,   k 2t+8,+9
        float2 e11 = *(const float2*)(base + 8 * 132 + 8);
        uint4 H, L;
        split2(e00, H.x, L.x);   // a0
        split2(e10, H.y, L.y);   // a1
        split2(e01, H.z, L.z);   // a2
        split2(e11, H.w, L.w);   // a3
        size_t MT = (size_t)(m0 >> 4) + mt;
        size_t KT = (size_t)kb * 8 + kt;
        size_t tb = (MT * 256 + KT) * 256;     // bf16 elems
        reinterpret_cast<uint4*>(g_xh + tb)[lane] = H;
        reinterpret_cast<uint4*>(g_xl + tb)[lane] = L;
    }
}

__global__ __launch_bounds__(256) void dequant_w_kernel(
    const float* __restrict__ wgt, const float* __restrict__ ws) {
    __shared__ float4 sm4[32 * 33];
    const int tid = threadIdx.x;
    const int kb  = blockIdx.x;
    const int n0  = blockIdx.y * 32;
    const float s = ws[(size_t)(n0 >> 7) * (KDIM / BLK) + kb];

#pragma unroll
    for (int j = 0; j < 4; ++j) {
        int i   = tid + 256 * j;
        int row = i >> 5;
        int c4  = i & 31;
        float4 v = *(const float4*)(wgt + (size_t)(n0 + row) * KDIM + kb * BLK + c4 * 4);
        v.x *= s; v.y *= s; v.z *= s; v.w *= s;
        sm4[row * 33 + c4] = v;
    }
    __syncthreads();

    const float* smf = (const float*)sm4;
    const int w = tid >> 5, lane = tid & 31;
    const int g = lane >> 2, t = lane & 3;
    // B tiles in block: 4 NT x 8 KT = 32 ; warp handles 4.
#pragma unroll
    for (int jj = 0; jj < 4; ++jj) {
        int T  = w * 4 + jj;
        int nt = T >> 3;
        int kt = T & 7;
        const float* base = smf + (nt * 8 + g) * 132 + kt * 16 + 2 * t;
        float2 e0 = *(const float2*)(base);      // k 2t, 2t+1
        float2 e1 = *(const float2*)(base + 8);  // k 2t+8, 2t+9
        uint2 H, L;
        split2(e0, H.x, L.x);   // b0
        split2(e1, H.y, L.y);   // b1
        size_t NT = (size_t)(n0 >> 3) + nt;
        size_t KT = (size_t)kb * 8 + kt;
        size_t tb = (NT * 256 + KT) * 128;
        reinterpret_cast<uint2*>(g_wh + tb)[lane] = H;
        reinterpret_cast<uint2*>(g_wl + tb)[lane] = L;
    }
}

// ---------------------------------------------------------------------------
// GEMM: y = xd . wd^T via bf16x3 (hh + hl + lh), fp32 accumulate.
// 256 threads, 8 warps 2(m) x 4(n), warp tile 64x32, mma.m16n8k16.bf16.
// MMA issue order grouped by plane-pair (16 independent accs per group) to
// kill the hh->hl->lh same-accumulator RAW chains.
// ---------------------------------------------------------------------------
__global__ __launch_bounds__(256, 2)
void gemm_bf16x3_kernel(float* __restrict__ out) {
    extern __shared__ char smem[];
    const uint32_t su = smem_u32(smem);
    const int tid  = threadIdx.x;
    const int wid  = tid >> 5;
    const int lane = tid & 31;
    const int warp_m = wid >> 2;
    const int warp_n = wid & 3;

    const int MT0 = blockIdx.y * 8;     // A tile rows (16m each)
    const int NT0 = blockIdx.x * 16;    // B tile rows (8n each)

    // ---- cp.async mapping: 4 A + 4 B 16B chunks per thread -----------------
    const char* aSrc[4];
    const char* bSrc[4];
    uint32_t aDst[4], bDst[4];
#pragma unroll
    for (int j = 0; j < 4; ++j) {
        int c = tid + 256 * j;                         // 0..1023
        {   // A: [plane(2)][mt(8)][64 chunks]
            int plane = c >> 9;
            int mt    = (c >> 6) & 7;
            int off   = (c & 63) * 16;
            const __nv_bfloat16* pl = plane ? g_xl : g_xh;
            // MT row stride = 256 KT * 512B = 131072B ; stage adds kt*1024B
            aSrc[j] = (const char*)pl + (size_t)(MT0 + mt) * 131072 + off;
            aDst[j] = (uint32_t)(plane * 8192 + mt * 1024 + off);
        }
        {   // B: [plane(2)][nt(16)][32 chunks]
            int plane = c >> 9;
            int nt    = (c >> 5) & 15;
            int off   = (c & 31) * 16;
            const __nv_bfloat16* pl = plane ? g_wl : g_wh;
            // NT row stride = 256 KT * 256B = 65536B ; stage adds kt*512B
            bSrc[j] = (const char*)pl + (size_t)(NT0 + nt) * 65536 + off;
            bDst[j] = (uint32_t)(A_STAGE_BYTES + plane * 8192 + nt * 512 + off);
        }
    }

    // ---- fragment LDS offsets ---------------------------------------------
    uint32_t aOff[4], bOff[4];
#pragma unroll
    for (int mi = 0; mi < 4; ++mi)
        aOff[mi] = (uint32_t)((warp_m * 4 + mi) * 1024 + lane * 16);
#pragma unroll
    for (int ni = 0; ni < 4; ++ni)
        bOff[ni] = (uint32_t)(A_STAGE_BYTES + (warp_n * 4 + ni) * 512 + lane * 8);

    float acc[4][4][4];
#pragma unroll
    for (int mi = 0; mi < 4; ++mi)
#pragma unroll
        for (int ni = 0; ni < 4; ++ni)
#pragma unroll
            for (int i = 0; i < 4; ++i) acc[mi][ni][i] = 0.0f;

    // ---- prologue ----------------------------------------------------------
#pragma unroll
    for (int p = 0; p < NSTAGE - 1; ++p) {
        const uint32_t sb = su + p * STAGE_BYTES;
#pragma unroll
        for (int j = 0; j < 4; ++j) cp_async16(sb + aDst[j], aSrc[j] + (size_t)p * 1024);
#pragma unroll
        for (int j = 0; j < 4; ++j) cp_async16(sb + bDst[j], bSrc[j] + (size_t)p * 512);
        CP_COMMIT();
    }

    // ---- mainloop ----------------------------------------------------------
    int stage = 0;
    for (int kt = 0; kt < NKITER; ++kt) {
        CP_WAIT(NSTAGE - 2);
        __syncthreads();

        const int pf = kt + NSTAGE - 1;
        if (pf < NKITER) {
            int pst = stage + (NSTAGE - 1);
            if (pst >= NSTAGE) pst -= NSTAGE;
            const uint32_t sb = su + pst * STAGE_BYTES;
#pragma unroll
            for (int j = 0; j < 4; ++j) cp_async16(sb + aDst[j], aSrc[j] + (size_t)pf * 1024);
#pragma unroll
            for (int j = 0; j < 4; ++j) cp_async16(sb + bDst[j], bSrc[j] + (size_t)pf * 512);
        }
        CP_COMMIT();

        const char* sb = smem + stage * STAGE_BYTES;
        if (++stage == NSTAGE) stage = 0;
#pragma unroll
        for (int ks = 0; ks < 2; ++ks) {          // two k16 steps per stage
            uint4 aH[4], aL[4];
            uint2 bH[4], bL[4];
#pragma unroll
            for (int mi = 0; mi < 4; ++mi) {
                aH[mi] = *reinterpret_cast<const uint4*>(sb + aOff[mi] + ks * 512);
                aL[mi] = *reinterpret_cast<const uint4*>(sb + aOff[mi] + ks * 512 + 8192);
            }
#pragma unroll
            for (int ni = 0; ni < 4; ++ni) {
                bH[ni] = *reinterpret_cast<const uint2*>(sb + bOff[ni] + ks * 256);
                bL[ni] = *reinterpret_cast<const uint2*>(sb + bOff[ni] + ks * 256 + 8192);
            }
            // Grouped issue: 16 independent accumulators per group — no RAW
            // chain shorter than 16 MMAs.
#pragma unroll
            for (int mi = 0; mi < 4; ++mi)
#pragma unroll
                for (int ni = 0; ni < 4; ++ni)
                    mma_bf16(acc[mi][ni], aH[mi], bH[ni]);   // hh
#pragma unroll
            for (int mi = 0; mi < 4; ++mi)
#pragma unroll
                for (int ni = 0; ni < 4; ++ni)
                    mma_bf16(acc[mi][ni], aH[mi], bL[ni]);   // hl
#pragma unroll
            for (int mi = 0; mi < 4; ++mi)
#pragma unroll
                for (int ni = 0; ni < 4; ++ni)
                    mma_bf16(acc[mi][ni], aL[mi], bH[ni]);   // lh
        }
    }

    // ---- epilogue: bf16-quantized values stored as fp32 --------------------
    const int m0 = blockIdx.y * BM;
    const int n0 = blockIdx.x * BN;
    const int mrow = lane >> 2;
    const int ncol = 2 * (lane & 3);
#pragma unroll
    for (int mi = 0; mi < 4; ++mi) {
        const int m = m0 + warp_m * 64 + mi * 16 + mrow;
#pragma unroll
        for (int ni = 0; ni < 4; ++ni) {
            const int n = n0 + warp_n * 32 + ni * 8 + ncol;
            float2 v01 = make_float2(bf16r(acc[mi][ni][0]), bf16r(acc[mi][ni][1]));
            float2 v23 = make_float2(bf16r(acc[mi][ni][2]), bf16r(acc[mi][ni][3]));
            *reinterpret_cast<float2*>(out + (size_t)m * NDIM + n)       = v01;
            *reinterpret_cast<float2*>(out + (size_t)(m + 8) * NDIM + n) = v23;
        }
    }
}

// ---------------------------------------------------------------------------
// Launch — bind inputs by element count (order-independent).
// ---------------------------------------------------------------------------
extern "C" void kernel_launch(void* const* d_in, const int* in_sizes, int n_in,
                              void* d_out, int out_size) {
    int idx_xs = -1, idx_ws = -1, big[2] = {-1, -1};
    int nbig = 0;
    for (int i = 0; i < n_in; ++i) {
        if (in_sizes[i] == MDIM * (KDIM / BLK))              idx_xs = i;  // 131072
        else if (in_sizes[i] == (NDIM / BLK) * (KDIM / BLK)) idx_ws = i;  // 1024
        else if (in_sizes[i] == MDIM * KDIM && nbig < 2)     big[nbig++] = i;
    }
    int idx_x, idx_w;
    if (idx_xs >= 0 && nbig == 2) {
        if      (big[0] == idx_xs - 1) { idx_x = big[0]; idx_w = big[1]; }
        else if (big[1] == idx_xs - 1) { idx_x = big[1]; idx_w = big[0]; }
        else if (big[0] == idx_xs + 1) { idx_x = big[0]; idx_w = big[1]; }
        else if (big[1] == idx_xs + 1) { idx_x = big[1]; idx_w = big[0]; }
        else                           { idx_x = big[0]; idx_w = big[1]; }
    } else { idx_x = 0; idx_xs = 1; idx_w = 2; idx_ws = 3; }

    const float* x  = (const float*)d_in[idx_x];
    const float* xs = (const float*)d_in[idx_xs];
    const float* w  = (const float*)d_in[idx_w];
    const float* ws = (const float*)d_in[idx_ws];
    float* y = (float*)d_out;                  // fp32 output buffer

    cudaFuncSetAttribute(gemm_bf16x3_kernel,
                         cudaFuncAttributeMaxDynamicSharedMemorySize, SMEM_BYTES);

    dim3 dq_grid(KDIM / BLK, MDIM / 32);       // (32, 128)
    dequant_x_kernel<<<dq_grid, 256>>>(x, xs);
    dequant_w_kernel<<<dq_grid, 256>>>(w, ws);

    dim3 grid(NDIM / BN, MDIM / BM);           // (32, 32)
    gemm_bf16x3_kernel<<<grid, 256, SMEM_BYTES>>>(y);
}

// round 15
// speedup vs baseline: 1.7808x; 1.0939x over previous
#include <cuda_runtime.h>
#include <cuda_bf16.h>
#include <cstdint>

// ---------------------------------------------------------------------------
// Problem constants
// ---------------------------------------------------------------------------
#define MDIM 4096
#define NDIM 4096
#define KDIM 4096
#define BLK  128

#define BM 128
#define BN 128
#define BK 32                      // K per pipeline stage (2 x k16 steps)
#define NSTAGE 3
#define NKITER (KDIM / BK)         // 128

// Fragment-native tiled layouts (mma.m16n8k16.bf16):
//   A tile = 16(m) x 16(k) bf16 = 512B, per-lane 8 halves at lane*16
//   B tile =  8(n) x 16(k) bf16 = 256B, per-lane 4 halves at lane*8
// Stage SMEM: A = [plane(2)][mt(8)][kt(2)][512B] = 16 KB
//             B = [plane(2)][nt(16)][kt(2)][256B] = 16 KB
#define A_STAGE_BYTES 16384
#define B_STAGE_BYTES 16384
#define STAGE_BYTES   (A_STAGE_BYTES + B_STAGE_BYTES)      // 32 KB
#define SMEM_BYTES    (NSTAGE * STAGE_BYTES)               // 96 KB -> 2 CTA/SM

// ---------------------------------------------------------------------------
// Scratch: hi/lo bf16 planes (scale-folded), fragment-ordered. 32 MB each.
// ---------------------------------------------------------------------------
__device__ __nv_bfloat16 g_xh[(size_t)MDIM * KDIM];
__device__ __nv_bfloat16 g_xl[(size_t)MDIM * KDIM];
__device__ __nv_bfloat16 g_wh[(size_t)NDIM * KDIM];
__device__ __nv_bfloat16 g_wl[(size_t)NDIM * KDIM];

// ---------------------------------------------------------------------------
// Helpers
// ---------------------------------------------------------------------------
__device__ __forceinline__ uint32_t smem_u32(const void* p) {
    uint32_t a;
    asm("{ .reg .u64 t; cvta.to.shared.u64 t, %1; cvt.u32.u64 %0, t; }"
        : "=r"(a) : "l"(p));
    return a;
}

__device__ __forceinline__ void cp_async16(uint32_t dst, const void* src) {
    asm volatile("cp.async.cg.shared.global [%0], [%1], 16;" :: "r"(dst), "l"(src));
}
#define CP_COMMIT()  asm volatile("cp.async.commit_group;" ::: "memory")
#define CP_WAIT(n)   asm volatile("cp.async.wait_group %0;" :: "n"(n) : "memory")

__device__ __forceinline__ void mma_bf16(float* c, const uint4& a, const uint2& b) {
    asm volatile(
        "mma.sync.aligned.m16n8k16.row.col.f32.bf16.bf16.f32 "
        "{%0,%1,%2,%3}, {%4,%5,%6,%7}, {%8,%9}, {%0,%1,%2,%3};"
        : "+f"(c[0]), "+f"(c[1]), "+f"(c[2]), "+f"(c[3])
        : "r"(a.x), "r"(a.y), "r"(a.z), "r"(a.w), "r"(b.x), "r"(b.y));
}

// Split a float2 into packed-bf16 hi and lo words (low half = .x).
__device__ __forceinline__ void split2(float2 v, uint32_t& h, uint32_t& l) {
    __nv_bfloat16 hx = __float2bfloat16(v.x);
    __nv_bfloat16 hy = __float2bfloat16(v.y);
    __nv_bfloat16 lx = __float2bfloat16(v.x - __bfloat162float(hx));
    __nv_bfloat16 ly = __float2bfloat16(v.y - __bfloat162float(hy));
    h = (uint32_t)__bfloat16_as_ushort(hx) | ((uint32_t)__bfloat16_as_ushort(hy) << 16);
    l = (uint32_t)__bfloat16_as_ushort(lx) | ((uint32_t)__bfloat16_as_ushort(ly) << 16);
}

// bf16-quantize a value but keep fp32 storage (reference casts to bf16; the
// harness output buffer is fp32).
__device__ __forceinline__ float bf16r(float v) {
    return __bfloat162float(__float2bfloat16(v));
}

// ---------------------------------------------------------------------------
// Dequant + split + fragment re-layout. Block = 32 rows x 128 k.
// SMEM staged with 33-float4 row stride (132 floats).
// ---------------------------------------------------------------------------
__global__ __launch_bounds__(256) void dequant_x_kernel(
    const float* __restrict__ x, const float* __restrict__ xs) {
    __shared__ float4 sm4[32 * 33];
    const int tid = threadIdx.x;
    const int kb  = blockIdx.x;            // 128-wide k block, 0..31
    const int m0  = blockIdx.y * 32;

#pragma unroll
    for (int j = 0; j < 4; ++j) {
        int i   = tid + 256 * j;
        int row = i >> 5;
        int c4  = i & 31;
        float s  = xs[(size_t)(m0 + row) * (KDIM / BLK) + kb];
        float4 v = *(const float4*)(x + (size_t)(m0 + row) * KDIM + kb * BLK + c4 * 4);
        v.x *= s; v.y *= s; v.z *= s; v.w *= s;
        sm4[row * 33 + c4] = v;
    }
    __syncthreads();

    const float* smf = (const float*)sm4;  // row stride 132 floats
    const int w = tid >> 5, lane = tid & 31;
    const int g = lane >> 2, t = lane & 3;
    // A tiles in block: 2 MT x 8 KT = 16 ; warp handles 2.
#pragma unroll
    for (int jj = 0; jj < 2; ++jj) {
        int T  = w * 2 + jj;
        int mt = T >> 3;
        int kt = T & 7;
        const float* base = smf + (mt * 16 + g) * 132 + kt * 16 + 2 * t;
        float2 e00 = *(const float2*)(base);             // row g,   k 2t,2t+1
        float2 e10 = *(const float2*)(base + 8 * 132);   // row g+8, k 2t,2t+1
        float2 e01 = *(const float2*)(base + 8);         // row g,   k 2t+8,+9
        float2 e11 = *(const float2*)(base + 8 * 132 + 8);
        uint4 H, L;
        split2(e00, H.x, L.x);   // a0
        split2(e10, H.y, L.y);   // a1
        split2(e01, H.z, L.z);   // a2
        split2(e11, H.w, L.w);   // a3
        size_t MT = (size_t)(m0 >> 4) + mt;
        size_t KT = (size_t)kb * 8 + kt;
        size_t tb = (MT * 256 + KT) * 256;     // bf16 elems
        reinterpret_cast<uint4*>(g_xh + tb)[lane] = H;
        reinterpret_cast<uint4*>(g_xl + tb)[lane] = L;
    }
}

__global__ __launch_bounds__(256) void dequant_w_kernel(
    const float* __restrict__ wgt, const float* __restrict__ ws) {
    __shared__ float4 sm4[32 * 33];
    const int tid = threadIdx.x;
    const int kb  = blockIdx.x;
    const int n0  = blockIdx.y * 32;
    const float s = ws[(size_t)(n0 >> 7) * (KDIM / BLK) + kb];

#pragma unroll
    for (int j = 0; j < 4; ++j) {
        int i   = tid + 256 * j;
        int row = i >> 5;
        int c4  = i & 31;
        float4 v = *(const float4*)(wgt + (size_t)(n0 + row) * KDIM + kb * BLK + c4 * 4);
        v.x *= s; v.y *= s; v.z *= s; v.w *= s;
        sm4[row * 33 + c4] = v;
    }
    __syncthreads();

    const float* smf = (const float*)sm4;
    const int w = tid >> 5, lane = tid & 31;
    const int g = lane >> 2, t = lane & 3;
    // B tiles in block: 4 NT x 8 KT = 32 ; warp handles 4.
#pragma unroll
    for (int jj = 0; jj < 4; ++jj) {
        int T  = w * 4 + jj;
        int nt = T >> 3;
        int kt = T & 7;
        const float* base = smf + (nt * 8 + g) * 132 + kt * 16 + 2 * t;
        float2 e0 = *(const float2*)(base);      // k 2t, 2t+1
        float2 e1 = *(const float2*)(base + 8);  // k 2t+8, 2t+9
        uint2 H, L;
        split2(e0, H.x, L.x);   // b0
        split2(e1, H.y, L.y);   // b1
        size_t NT = (size_t)(n0 >> 3) + nt;
        size_t KT = (size_t)kb * 8 + kt;
        size_t tb = (NT * 256 + KT) * 128;
        reinterpret_cast<uint2*>(g_wh + tb)[lane] = H;
        reinterpret_cast<uint2*>(g_wl + tb)[lane] = L;
    }
}

// ---------------------------------------------------------------------------
// GEMM: y = xd . wd^T via bf16x3 (hh + hl + lh), fp32 accumulate.
// 256 threads, 8 warps 2(m) x 4(n), warp tile 64x32, mma.m16n8k16.bf16.
// Issue-stream smoothing: per-group fragment loads, cp.async interleaved
// between MMA groups, rotating compile-time stage bases.
// ---------------------------------------------------------------------------
__global__ __launch_bounds__(256, 2)
void gemm_bf16x3_kernel(float* __restrict__ out) {
    extern __shared__ char smem[];
    const uint32_t su = smem_u32(smem);
    const int tid  = threadIdx.x;
    const int wid  = tid >> 5;
    const int lane = tid & 31;
    const int warp_m = wid >> 2;
    const int warp_n = wid & 3;

    const int MT0 = blockIdx.y * 8;     // A tile rows (16m each)
    const int NT0 = blockIdx.x * 16;    // B tile rows (8n each)

    // ---- cp.async mapping: 4 A + 4 B 16B chunks per thread -----------------
    const char* aSrc[4];                // advanced per-kt by += 1024
    const char* bSrc[4];                // advanced per-kt by += 512
    uint32_t aDst[4], bDst[4];          // stage-relative
#pragma unroll
    for (int j = 0; j < 4; ++j) {
        int c = tid + 256 * j;                         // 0..1023
        {   // A: [plane(2)][mt(8)][64 chunks]
            int plane = c >> 9;
            int mt    = (c >> 6) & 7;
            int off   = (c & 63) * 16;
            const __nv_bfloat16* pl = plane ? g_xl : g_xh;
            // MT row stride = 256 KT * 512B = 131072B ; stage adds kt*1024B
            aSrc[j] = (const char*)pl + (size_t)(MT0 + mt) * 131072 + off;
            aDst[j] = (uint32_t)(plane * 8192 + mt * 1024 + off);
        }
        {   // B: [plane(2)][nt(16)][32 chunks]
            int plane = c >> 9;
            int nt    = (c >> 5) & 15;
            int off   = (c & 31) * 16;
            const __nv_bfloat16* pl = plane ? g_wl : g_wh;
            // NT row stride = 256 KT * 256B = 65536B ; stage adds kt*512B
            bSrc[j] = (const char*)pl + (size_t)(NT0 + nt) * 65536 + off;
            bDst[j] = (uint32_t)(A_STAGE_BYTES + plane * 8192 + nt * 512 + off);
        }
    }

    // ---- fragment LDS offsets (stage-relative) -----------------------------
    uint32_t aOff[4], bOff[4];
#pragma unroll
    for (int mi = 0; mi < 4; ++mi)
        aOff[mi] = (uint32_t)((warp_m * 4 + mi) * 1024 + lane * 16);
#pragma unroll
    for (int ni = 0; ni < 4; ++ni)
        bOff[ni] = (uint32_t)(A_STAGE_BYTES + (warp_n * 4 + ni) * 512 + lane * 8);

    float acc[4][4][4];
#pragma unroll
    for (int mi = 0; mi < 4; ++mi)
#pragma unroll
        for (int ni = 0; ni < 4; ++ni)
#pragma unroll
            for (int i = 0; i < 4; ++i) acc[mi][ni][i] = 0.0f;

    // ---- prologue: fill stages 0,1 -----------------------------------------
#pragma unroll
    for (int p = 0; p < NSTAGE - 1; ++p) {
        const uint32_t sb = su + p * STAGE_BYTES;
#pragma unroll
        for (int j = 0; j < 4; ++j) cp_async16(sb + aDst[j], aSrc[j] + (size_t)p * 1024);
#pragma unroll
        for (int j = 0; j < 4; ++j) cp_async16(sb + bDst[j], bSrc[j] + (size_t)p * 512);
        CP_COMMIT();
    }
    // advance prefetch pointers to pf = NSTAGE-1 = 2
#pragma unroll
    for (int j = 0; j < 4; ++j) { aSrc[j] += 2 * 1024; bSrc[j] += 2 * 512; }

    // ---- rotating stage bases ---------------------------------------------
    const char* rd  = smem;                          // read stage (kt % 3 = 0)
    const char* rd1 = smem + STAGE_BYTES;
    const char* rd2 = smem + 2 * STAGE_BYTES;
    uint32_t    wr  = su + 2 * STAGE_BYTES;          // prefetch stage (kt+2)%3

    // ---- mainloop ----------------------------------------------------------
    for (int kt = 0; kt < NKITER; ++kt) {
        CP_WAIT(NSTAGE - 2);
        __syncthreads();
        const bool pf_ok = kt < NKITER - (NSTAGE - 1);

#pragma unroll
        for (int ks = 0; ks < 2; ++ks) {          // two k16 steps per stage
            const char* sb = rd;
            const int ao = ks * 512;
            const int bo = ks * 256;

            // ---- group hh: load aH,bH then 16 independent MMAs -------------
            uint4 aH[4];
            uint2 bH[4];
#pragma unroll
            for (int mi = 0; mi < 4; ++mi)
                aH[mi] = *reinterpret_cast<const uint4*>(sb + aOff[mi] + ao);
#pragma unroll
            for (int ni = 0; ni < 4; ++ni)
                bH[ni] = *reinterpret_cast<const uint2*>(sb + bOff[ni] + bo);
#pragma unroll
            for (int mi = 0; mi < 4; ++mi)
#pragma unroll
                for (int ni = 0; ni < 4; ++ni)
                    mma_bf16(acc[mi][ni], aH[mi], bH[ni]);   // hh

            // interleave: A-half prefetch after group 1 of ks=0
            if (ks == 0 && pf_ok) {
#pragma unroll
                for (int j = 0; j < 4; ++j) cp_async16(wr + aDst[j], aSrc[j]);
            }

            // ---- group hl: load bL, reuse aH -------------------------------
            uint2 bL[4];
#pragma unroll
            for (int ni = 0; ni < 4; ++ni)
                bL[ni] = *reinterpret_cast<const uint2*>(sb + bOff[ni] + bo + 8192);
#pragma unroll
            for (int mi = 0; mi < 4; ++mi)
#pragma unroll
                for (int ni = 0; ni < 4; ++ni)
                    mma_bf16(acc[mi][ni], aH[mi], bL[ni]);   // hl

            // interleave: B-half prefetch after group 2 of ks=0
            if (ks == 0 && pf_ok) {
#pragma unroll
                for (int j = 0; j < 4; ++j) cp_async16(wr + bDst[j], bSrc[j]);
            }

            // ---- group lh: load aL, reuse bH -------------------------------
            uint4 aL[4];
#pragma unroll
            for (int mi = 0; mi < 4; ++mi)
                aL[mi] = *reinterpret_cast<const uint4*>(sb + aOff[mi] + ao + 8192);
#pragma unroll
            for (int mi = 0; mi < 4; ++mi)
#pragma unroll
                for (int ni = 0; ni < 4; ++ni)
                    mma_bf16(acc[mi][ni], aL[mi], bH[ni]);   // lh
        }
        CP_COMMIT();

        // advance prefetch pointers and rotate stages
#pragma unroll
        for (int j = 0; j < 4; ++j) { aSrc[j] += 1024; bSrc[j] += 512; }
        const char* t0 = rd;
        rd  = rd1; rd1 = rd2; rd2 = t0;
        wr  = su + (uint32_t)(rd2 - smem);
    }

    // ---- epilogue: bf16-quantized values stored as fp32 --------------------
    const int m0 = blockIdx.y * BM;
    const int n0 = blockIdx.x * BN;
    const int mrow = lane >> 2;
    const int ncol = 2 * (lane & 3);
#pragma unroll
    for (int mi = 0; mi < 4; ++mi) {
        const int m = m0 + warp_m * 64 + mi * 16 + mrow;
#pragma unroll
        for (int ni = 0; ni < 4; ++ni) {
            const int n = n0 + warp_n * 32 + ni * 8 + ncol;
            float2 v01 = make_float2(bf16r(acc[mi][ni][0]), bf16r(acc[mi][ni][1]));
            float2 v23 = make_float2(bf16r(acc[mi][ni][2]), bf16r(acc[mi][ni][3]));
            *reinterpret_cast<float2*>(out + (size_t)m * NDIM + n)       = v01;
            *reinterpret_cast<float2*>(out + (size_t)(m + 8) * NDIM + n) = v23;
        }
    }
}

// ---------------------------------------------------------------------------
// Launch — bind inputs by element count (order-independent).
// ---------------------------------------------------------------------------
extern "C" void kernel_launch(void* const* d_in, const int* in_sizes, int n_in,
                              void* d_out, int out_size) {
    int idx_xs = -1, idx_ws = -1, big[2] = {-1, -1};
    int nbig = 0;
    for (int i = 0; i < n_in; ++i) {
        if (in_sizes[i] == MDIM * (KDIM / BLK))              idx_xs = i;  // 131072
        else if (in_sizes[i] == (NDIM / BLK) * (KDIM / BLK)) idx_ws = i;  // 1024
        else if (in_sizes[i] == MDIM * KDIM && nbig < 2)     big[nbig++] = i;
    }
    int idx_x, idx_w;
    if (idx_xs >= 0 && nbig == 2) {
        if      (big[0] == idx_xs - 1) { idx_x = big[0]; idx_w = big[1]; }
        else if (big[1] == idx_xs - 1) { idx_x = big[1]; idx_w = big[0]; }
        else if (big[0] == idx_xs + 1) { idx_x = big[0]; idx_w = big[1]; }
        else if (big[1] == idx_xs + 1) { idx_x = big[1]; idx_w = big[0]; }
        else                           { idx_x = big[0]; idx_w = big[1]; }
    } else { idx_x = 0; idx_xs = 1; idx_w = 2; idx_ws = 3; }

    const float* x  = (const float*)d_in[idx_x];
    const float* xs = (const float*)d_in[idx_xs];
    const float* w  = (const float*)d_in[idx_w];
    const float* ws = (const float*)d_in[idx_ws];
    float* y = (float*)d_out;                  // fp32 output buffer

    cudaFuncSetAttribute(gemm_bf16x3_kernel,
                         cudaFuncAttributeMaxDynamicSharedMemorySize, SMEM_BYTES);

    dim3 dq_grid(KDIM / BLK, MDIM / 32);       // (32, 128)
    dequant_x_kernel<<<dq_grid, 256>>>(x, xs);
    dequant_w_kernel<<<dq_grid, 256>>>(w, ws);

    dim3 grid(NDIM / BN, MDIM / BM);           // (32, 32)
    gemm_bf16x3_kernel<<<grid, 256, SMEM_BYTES>>>(y);
}